// round 2
// baseline (speedup 1.0000x reference)
#include <cuda_runtime.h>

#define N_NODES 200000
#define D_IN    256
#define D_OUT   256
#define BATCH   4096
#define K1      25
#define K2      10
#define M_L1    (BATCH * (1 + K2))   // 45056

// ---------------- scratch (no allocations allowed) ----------------
__device__ float g_X1[(size_t)M_L1 * 2 * D_IN];   // [45056, 512]  ~92 MB
__device__ float g_h1[(size_t)M_L1 * D_OUT];      // [45056, 256]  ~46 MB
__device__ float g_X2[(size_t)BATCH * 2 * D_OUT]; // [4096, 512]   ~8 MB
__device__ int   g_is64;                          // index dtype flag

// ---------------- index dtype probe ----------------
// If the harness passes int64, values read as int64 are all in [0, N_NODES).
// If it passes int32, an int64 read merges two int32s -> almost surely huge.
__global__ void detect_idx_dtype(const void* __restrict__ nb) {
    const long long* p = (const long long*)nb;
    int ok64 = 1;
    #pragma unroll
    for (int i = 0; i < 64; i++) {
        long long v = p[i];
        if (v < 0 || v >= (long long)N_NODES) ok64 = 0;
    }
    g_is64 = ok64;
}

__device__ __forceinline__ int get_idx(const void* __restrict__ p, int i) {
    if (g_is64) return (int)((const long long*)p)[i];
    return ((const int*)p)[i];
}

// ---------------- layer-1 gather + mean ----------------
// block = one l1 row (256 threads, one per feature dim)
__global__ void gather1_kernel(const float* __restrict__ features,
                               const void* __restrict__ nodes_batch,
                               const void* __restrict__ neigh2,
                               const void* __restrict__ neigh1) {
    int m = blockIdx.x;
    int t = threadIdx.x;  // 0..255
    __shared__ int idx[K1 + 1];
    if (t < K1) idx[t + 1] = get_idx(neigh1, m * K1 + t);
    if (t == K1) idx[0] = (m < BATCH) ? get_idx(nodes_batch, m)
                                      : get_idx(neigh2, m - BATCH);
    __syncthreads();

    float selfv = features[(size_t)idx[0] * D_IN + t];
    float acc = 0.f;
    #pragma unroll
    for (int k = 0; k < K1; k++)
        acc += features[(size_t)idx[k + 1] * D_IN + t];

    size_t base = (size_t)m * (2 * D_IN);
    g_X1[base + t]        = selfv;
    g_X1[base + D_IN + t] = acc * (1.0f / K1);
}

// ---------------- layer-2 concat build ----------------
__global__ void build_x2_kernel() {
    int b = blockIdx.x;    // 0..4095
    int t = threadIdx.x;   // 0..255
    float selfv = g_h1[(size_t)b * D_OUT + t];
    float acc = 0.f;
    #pragma unroll
    for (int j = 0; j < K2; j++)
        acc += g_h1[(size_t)(BATCH + b * K2 + j) * D_OUT + t];
    size_t base = (size_t)b * (2 * D_OUT);
    g_X2[base + t]         = selfv;
    g_X2[base + D_OUT + t] = acc * (1.0f / K2);
}

// ---------------- fp32 tiled GEMM: C = relu_opt(A @ W^T) ----------------
// A: [Mrows, Kdim] row-major, W: [Ncols, Kdim] row-major (so both K-contig)
// BM=BN=64, BK=16, 256 threads, 4x4 micro-tile per thread.
template <bool RELU>
__global__ void sgemm_relu_kernel(const float* __restrict__ A,
                                  const float* __restrict__ W,
                                  float* __restrict__ C,
                                  int Mrows, int Kdim, int Ncols) {
    __shared__ float As[16][64];
    __shared__ float Ws[16][64];

    int tid = threadIdx.x;
    int tx = tid & 15;        // 0..15  (n direction)
    int ty = tid >> 4;        // 0..15  (m direction)
    int bm = blockIdx.x * 64;
    int bn = blockIdx.y * 64;

    int lr = tid >> 2;         // 0..63 : row within tile for loads
    int lk = (tid & 3) * 4;    // 0,4,8,12 : k offset for float4 load

    const float* Aptr = A + (size_t)(bm + lr) * Kdim + lk;
    const float* Wptr = W + (size_t)(bn + lr) * Kdim + lk;

    float acc[4][4];
    #pragma unroll
    for (int i = 0; i < 4; i++)
        #pragma unroll
        for (int j = 0; j < 4; j++) acc[i][j] = 0.f;

    for (int k0 = 0; k0 < Kdim; k0 += 16) {
        float4 a4 = *(const float4*)(Aptr + k0);
        float4 w4 = *(const float4*)(Wptr + k0);
        As[lk + 0][lr] = a4.x; As[lk + 1][lr] = a4.y;
        As[lk + 2][lr] = a4.z; As[lk + 3][lr] = a4.w;
        Ws[lk + 0][lr] = w4.x; Ws[lk + 1][lr] = w4.y;
        Ws[lk + 2][lr] = w4.z; Ws[lk + 3][lr] = w4.w;
        __syncthreads();

        #pragma unroll
        for (int k = 0; k < 16; k++) {
            float4 ra = *(const float4*)&As[k][ty * 4];
            float4 rb = *(const float4*)&Ws[k][tx * 4];
            float av[4] = {ra.x, ra.y, ra.z, ra.w};
            float bv[4] = {rb.x, rb.y, rb.z, rb.w};
            #pragma unroll
            for (int i = 0; i < 4; i++)
                #pragma unroll
                for (int j = 0; j < 4; j++)
                    acc[i][j] = fmaf(av[i], bv[j], acc[i][j]);
        }
        __syncthreads();
    }

    #pragma unroll
    for (int i = 0; i < 4; i++) {
        int row = bm + ty * 4 + i;
        float4 out;
        float v0 = acc[i][0], v1 = acc[i][1], v2 = acc[i][2], v3 = acc[i][3];
        if (RELU) {
            v0 = fmaxf(v0, 0.f); v1 = fmaxf(v1, 0.f);
            v2 = fmaxf(v2, 0.f); v3 = fmaxf(v3, 0.f);
        }
        out.x = v0; out.y = v1; out.z = v2; out.w = v3;
        *(float4*)&C[(size_t)row * Ncols + bn + tx * 4] = out;
    }
}

// ---------------- launch ----------------
extern "C" void kernel_launch(void* const* d_in, const int* in_sizes, int n_in,
                              void* d_out, int out_size) {
    const float* features    = (const float*)d_in[0];
    const float* W1          = (const float*)d_in[1];
    const float* W2          = (const float*)d_in[2];
    const void*  nodes_batch = d_in[3];
    const void*  neigh2      = d_in[4];
    const void*  neigh1      = d_in[5];
    float* out = (float*)d_out;

    float *pX1, *pH1, *pX2;
    cudaGetSymbolAddress((void**)&pX1, g_X1);
    cudaGetSymbolAddress((void**)&pH1, g_h1);
    cudaGetSymbolAddress((void**)&pX2, g_X2);

    detect_idx_dtype<<<1, 1>>>(nodes_batch);
    gather1_kernel<<<M_L1, 256>>>(features, nodes_batch, neigh2, neigh1);

    // h1 = relu(X1 @ W1^T)  : [45056, 512] x [256, 512]^T -> [45056, 256]
    sgemm_relu_kernel<true><<<dim3(M_L1 / 64, D_OUT / 64), 256>>>(
        pX1, W1, pH1, M_L1, 2 * D_IN, D_OUT);

    build_x2_kernel<<<BATCH, 256>>>();

    // h2 = relu(X2 @ W2^T)  : [4096, 512] x [256, 512]^T -> [4096, 256]
    sgemm_relu_kernel<true><<<dim3(BATCH / 64, D_OUT / 64), 256>>>(
        pX2, W2, out, BATCH, 2 * D_OUT, D_OUT);
}

// round 3
// speedup vs baseline: 1.0399x; 1.0399x over previous
#include <cuda_runtime.h>

#define N_NODES 200000
#define D_IN    256
#define D_OUT   256
#define BATCH   4096
#define K1      25
#define K2      10
#define M_L1    (BATCH * (1 + K2))   // 45056

// ---------------- scratch (no allocations allowed) ----------------
__device__ float g_X1[(size_t)M_L1 * 2 * D_IN];   // [45056, 512]  ~92 MB
__device__ float g_h1[(size_t)M_L1 * D_OUT];      // [45056, 256]  ~46 MB
__device__ float g_X2[(size_t)BATCH * 2 * D_OUT]; // [4096, 512]   ~8 MB
__device__ int   g_is64;                          // index dtype flag

// ---------------- index dtype probe ----------------
// If the harness passes int64, values read as int64 are all in [0, N_NODES).
// If it passes int32, an int64 read merges two int32s -> almost surely huge.
__global__ void detect_idx_dtype(const void* __restrict__ nb) {
    const long long* p = (const long long*)nb;
    int ok64 = 1;
    #pragma unroll
    for (int i = 0; i < 64; i++) {
        long long v = p[i];
        if (v < 0 || v >= (long long)N_NODES) ok64 = 0;
    }
    g_is64 = ok64;
}

__device__ __forceinline__ int get_idx(const void* __restrict__ p, int i) {
    if (g_is64) return (int)((const long long*)p)[i];
    return ((const int*)p)[i];
}

// ---------------- layer-1 gather + mean ----------------
// block = one l1 row (256 threads, one per feature dim)
__global__ void gather1_kernel(const float* __restrict__ features,
                               const void* __restrict__ nodes_batch,
                               const void* __restrict__ neigh2,
                               const void* __restrict__ neigh1) {
    int m = blockIdx.x;
    int t = threadIdx.x;  // 0..255
    __shared__ int idx[K1 + 1];
    if (t < K1) idx[t + 1] = get_idx(neigh1, m * K1 + t);
    if (t == K1) idx[0] = (m < BATCH) ? get_idx(nodes_batch, m)
                                      : get_idx(neigh2, m - BATCH);
    __syncthreads();

    float selfv = features[(size_t)idx[0] * D_IN + t];
    float acc = 0.f;
    #pragma unroll
    for (int k = 0; k < K1; k++)
        acc += features[(size_t)idx[k + 1] * D_IN + t];

    size_t base = (size_t)m * (2 * D_IN);
    g_X1[base + t]        = selfv;
    g_X1[base + D_IN + t] = acc * (1.0f / K1);
}

// ---------------- layer-2 concat build ----------------
__global__ void build_x2_kernel() {
    int b = blockIdx.x;    // 0..4095
    int t = threadIdx.x;   // 0..255
    float selfv = g_h1[(size_t)b * D_OUT + t];
    float acc = 0.f;
    #pragma unroll
    for (int j = 0; j < K2; j++)
        acc += g_h1[(size_t)(BATCH + b * K2 + j) * D_OUT + t];
    size_t base = (size_t)b * (2 * D_OUT);
    g_X2[base + t]         = selfv;
    g_X2[base + D_OUT + t] = acc * (1.0f / K2);
}

// ---------------- fp32 tiled GEMM: C = relu_opt(A @ W^T) ----------------
// A: [Mrows, Kdim] row-major, W: [Ncols, Kdim] row-major (so both K-contig)
// BM=BN=64, BK=16, 256 threads, 4x4 micro-tile per thread.
template <bool RELU>
__global__ void sgemm_relu_kernel(const float* __restrict__ A,
                                  const float* __restrict__ W,
                                  float* __restrict__ C,
                                  int Mrows, int Kdim, int Ncols) {
    __shared__ float As[16][64];
    __shared__ float Ws[16][64];

    int tid = threadIdx.x;
    int tx = tid & 15;        // 0..15  (n direction)
    int ty = tid >> 4;        // 0..15  (m direction)
    int bm = blockIdx.x * 64;
    int bn = blockIdx.y * 64;

    int lr = tid >> 2;         // 0..63 : row within tile for loads
    int lk = (tid & 3) * 4;    // 0,4,8,12 : k offset for float4 load

    const float* Aptr = A + (size_t)(bm + lr) * Kdim + lk;
    const float* Wptr = W + (size_t)(bn + lr) * Kdim + lk;

    float acc[4][4];
    #pragma unroll
    for (int i = 0; i < 4; i++)
        #pragma unroll
        for (int j = 0; j < 4; j++) acc[i][j] = 0.f;

    for (int k0 = 0; k0 < Kdim; k0 += 16) {
        float4 a4 = *(const float4*)(Aptr + k0);
        float4 w4 = *(const float4*)(Wptr + k0);
        As[lk + 0][lr] = a4.x; As[lk + 1][lr] = a4.y;
        As[lk + 2][lr] = a4.z; As[lk + 3][lr] = a4.w;
        Ws[lk + 0][lr] = w4.x; Ws[lk + 1][lr] = w4.y;
        Ws[lk + 2][lr] = w4.z; Ws[lk + 3][lr] = w4.w;
        __syncthreads();

        #pragma unroll
        for (int k = 0; k < 16; k++) {
            float4 ra = *(const float4*)&As[k][ty * 4];
            float4 rb = *(const float4*)&Ws[k][tx * 4];
            float av[4] = {ra.x, ra.y, ra.z, ra.w};
            float bv[4] = {rb.x, rb.y, rb.z, rb.w};
            #pragma unroll
            for (int i = 0; i < 4; i++)
                #pragma unroll
                for (int j = 0; j < 4; j++)
                    acc[i][j] = fmaf(av[i], bv[j], acc[i][j]);
        }
        __syncthreads();
    }

    #pragma unroll
    for (int i = 0; i < 4; i++) {
        int row = bm + ty * 4 + i;
        float4 out;
        float v0 = acc[i][0], v1 = acc[i][1], v2 = acc[i][2], v3 = acc[i][3];
        if (RELU) {
            v0 = fmaxf(v0, 0.f); v1 = fmaxf(v1, 0.f);
            v2 = fmaxf(v2, 0.f); v3 = fmaxf(v3, 0.f);
        }
        out.x = v0; out.y = v1; out.z = v2; out.w = v3;
        *(float4*)&C[(size_t)row * Ncols + bn + tx * 4] = out;
    }
}

// ---------------- launch ----------------
extern "C" void kernel_launch(void* const* d_in, const int* in_sizes, int n_in,
                              void* d_out, int out_size) {
    const float* features    = (const float*)d_in[0];
    const float* W1          = (const float*)d_in[1];
    const float* W2          = (const float*)d_in[2];
    const void*  nodes_batch = d_in[3];
    const void*  neigh2      = d_in[4];
    const void*  neigh1      = d_in[5];
    float* out = (float*)d_out;

    float *pX1, *pH1, *pX2;
    cudaGetSymbolAddress((void**)&pX1, g_X1);
    cudaGetSymbolAddress((void**)&pH1, g_h1);
    cudaGetSymbolAddress((void**)&pX2, g_X2);

    detect_idx_dtype<<<1, 1>>>(nodes_batch);
    gather1_kernel<<<M_L1, 256>>>(features, nodes_batch, neigh2, neigh1);

    // h1 = relu(X1 @ W1^T)  : [45056, 512] x [256, 512]^T -> [45056, 256]
    sgemm_relu_kernel<true><<<dim3(M_L1 / 64, D_OUT / 64), 256>>>(
        pX1, W1, pH1, M_L1, 2 * D_IN, D_OUT);

    build_x2_kernel<<<BATCH, 256>>>();

    // h2 = relu(X2 @ W2^T)  : [4096, 512] x [256, 512]^T -> [4096, 256]
    sgemm_relu_kernel<true><<<dim3(BATCH / 64, D_OUT / 64), 256>>>(
        pX2, W2, out, BATCH, 2 * D_OUT, D_OUT);
}

// round 4
// speedup vs baseline: 1.0426x; 1.0026x over previous
#include <cuda_runtime.h>

#define N_NODES 200000
#define D_IN    256
#define D_OUT   256
#define BATCH   4096
#define K1      25
#define K2      10
#define M_L1    (BATCH * (1 + K2))   // 45056

// ---------------- scratch (no allocations allowed) ----------------
__device__ float g_X1[(size_t)M_L1 * 2 * D_IN];   // [45056, 512]  ~92 MB
__device__ float g_h1[(size_t)M_L1 * D_OUT];      // [45056, 256]  ~46 MB
__device__ float g_X2[(size_t)BATCH * 2 * D_OUT]; // [4096, 512]   ~8 MB
__device__ int   g_is64;                          // index dtype flag

// ---------------- index dtype probe ----------------
// If the harness passes int64, values read as int64 are all in [0, N_NODES).
// If it passes int32, an int64 read merges two int32s -> almost surely huge.
__global__ void detect_idx_dtype(const void* __restrict__ nb) {
    const long long* p = (const long long*)nb;
    int ok64 = 1;
    #pragma unroll
    for (int i = 0; i < 64; i++) {
        long long v = p[i];
        if (v < 0 || v >= (long long)N_NODES) ok64 = 0;
    }
    g_is64 = ok64;
}

__device__ __forceinline__ int get_idx(const void* __restrict__ p, int i) {
    if (g_is64) return (int)((const long long*)p)[i];
    return ((const int*)p)[i];
}

// ---------------- layer-1 gather + mean ----------------
// block = one l1 row (256 threads, one per feature dim)
__global__ void gather1_kernel(const float* __restrict__ features,
                               const void* __restrict__ nodes_batch,
                               const void* __restrict__ neigh2,
                               const void* __restrict__ neigh1) {
    int m = blockIdx.x;
    int t = threadIdx.x;  // 0..255
    __shared__ int idx[K1 + 1];
    if (t < K1) idx[t + 1] = get_idx(neigh1, m * K1 + t);
    if (t == K1) idx[0] = (m < BATCH) ? get_idx(nodes_batch, m)
                                      : get_idx(neigh2, m - BATCH);
    __syncthreads();

    float selfv = features[(size_t)idx[0] * D_IN + t];
    float acc = 0.f;
    #pragma unroll
    for (int k = 0; k < K1; k++)
        acc += features[(size_t)idx[k + 1] * D_IN + t];

    size_t base = (size_t)m * (2 * D_IN);
    g_X1[base + t]        = selfv;
    g_X1[base + D_IN + t] = acc * (1.0f / K1);
}

// ---------------- layer-2 concat build ----------------
__global__ void build_x2_kernel() {
    int b = blockIdx.x;    // 0..4095
    int t = threadIdx.x;   // 0..255
    float selfv = g_h1[(size_t)b * D_OUT + t];
    float acc = 0.f;
    #pragma unroll
    for (int j = 0; j < K2; j++)
        acc += g_h1[(size_t)(BATCH + b * K2 + j) * D_OUT + t];
    size_t base = (size_t)b * (2 * D_OUT);
    g_X2[base + t]         = selfv;
    g_X2[base + D_OUT + t] = acc * (1.0f / K2);
}

// ---------------- fp32 tiled GEMM: C = relu_opt(A @ W^T) ----------------
// A: [Mrows, Kdim] row-major, W: [Ncols, Kdim] row-major (so both K-contig)
// BM=BN=64, BK=16, 256 threads, 4x4 micro-tile per thread.
template <bool RELU>
__global__ void sgemm_relu_kernel(const float* __restrict__ A,
                                  const float* __restrict__ W,
                                  float* __restrict__ C,
                                  int Mrows, int Kdim, int Ncols) {
    __shared__ float As[16][64];
    __shared__ float Ws[16][64];

    int tid = threadIdx.x;
    int tx = tid & 15;        // 0..15  (n direction)
    int ty = tid >> 4;        // 0..15  (m direction)
    int bm = blockIdx.x * 64;
    int bn = blockIdx.y * 64;

    int lr = tid >> 2;         // 0..63 : row within tile for loads
    int lk = (tid & 3) * 4;    // 0,4,8,12 : k offset for float4 load

    const float* Aptr = A + (size_t)(bm + lr) * Kdim + lk;
    const float* Wptr = W + (size_t)(bn + lr) * Kdim + lk;

    float acc[4][4];
    #pragma unroll
    for (int i = 0; i < 4; i++)
        #pragma unroll
        for (int j = 0; j < 4; j++) acc[i][j] = 0.f;

    for (int k0 = 0; k0 < Kdim; k0 += 16) {
        float4 a4 = *(const float4*)(Aptr + k0);
        float4 w4 = *(const float4*)(Wptr + k0);
        As[lk + 0][lr] = a4.x; As[lk + 1][lr] = a4.y;
        As[lk + 2][lr] = a4.z; As[lk + 3][lr] = a4.w;
        Ws[lk + 0][lr] = w4.x; Ws[lk + 1][lr] = w4.y;
        Ws[lk + 2][lr] = w4.z; Ws[lk + 3][lr] = w4.w;
        __syncthreads();

        #pragma unroll
        for (int k = 0; k < 16; k++) {
            float4 ra = *(const float4*)&As[k][ty * 4];
            float4 rb = *(const float4*)&Ws[k][tx * 4];
            float av[4] = {ra.x, ra.y, ra.z, ra.w};
            float bv[4] = {rb.x, rb.y, rb.z, rb.w};
            #pragma unroll
            for (int i = 0; i < 4; i++)
                #pragma unroll
                for (int j = 0; j < 4; j++)
                    acc[i][j] = fmaf(av[i], bv[j], acc[i][j]);
        }
        __syncthreads();
    }

    #pragma unroll
    for (int i = 0; i < 4; i++) {
        int row = bm + ty * 4 + i;
        float4 out;
        float v0 = acc[i][0], v1 = acc[i][1], v2 = acc[i][2], v3 = acc[i][3];
        if (RELU) {
            v0 = fmaxf(v0, 0.f); v1 = fmaxf(v1, 0.f);
            v2 = fmaxf(v2, 0.f); v3 = fmaxf(v3, 0.f);
        }
        out.x = v0; out.y = v1; out.z = v2; out.w = v3;
        *(float4*)&C[(size_t)row * Ncols + bn + tx * 4] = out;
    }
}

// ---------------- launch ----------------
extern "C" void kernel_launch(void* const* d_in, const int* in_sizes, int n_in,
                              void* d_out, int out_size) {
    const float* features    = (const float*)d_in[0];
    const float* W1          = (const float*)d_in[1];
    const float* W2          = (const float*)d_in[2];
    const void*  nodes_batch = d_in[3];
    const void*  neigh2      = d_in[4];
    const void*  neigh1      = d_in[5];
    float* out = (float*)d_out;

    float *pX1, *pH1, *pX2;
    cudaGetSymbolAddress((void**)&pX1, g_X1);
    cudaGetSymbolAddress((void**)&pH1, g_h1);
    cudaGetSymbolAddress((void**)&pX2, g_X2);

    detect_idx_dtype<<<1, 1>>>(nodes_batch);
    gather1_kernel<<<M_L1, 256>>>(features, nodes_batch, neigh2, neigh1);

    // h1 = relu(X1 @ W1^T)  : [45056, 512] x [256, 512]^T -> [45056, 256]
    sgemm_relu_kernel<true><<<dim3(M_L1 / 64, D_OUT / 64), 256>>>(
        pX1, W1, pH1, M_L1, 2 * D_IN, D_OUT);

    build_x2_kernel<<<BATCH, 256>>>();

    // h2 = relu(X2 @ W2^T)  : [4096, 512] x [256, 512]^T -> [4096, 256]
    sgemm_relu_kernel<true><<<dim3(BATCH / 64, D_OUT / 64), 256>>>(
        pX2, W2, out, BATCH, 2 * D_OUT, D_OUT);
}

// round 6
// speedup vs baseline: 1.3694x; 1.3135x over previous
#include <cuda_runtime.h>
#include <cuda_bf16.h>
#include <cstdint>

#define N_NODES 200000
#define D_IN    256
#define D_OUT   256
#define BATCH   4096
#define K1      25
#define K2      10
#define M_L1    (BATCH * (1 + K2))   // 45056
#define KDIM    512                  // concat(self, agg) width

// ---------------- scratch (no allocations allowed) ----------------
__device__ __align__(16) __nv_bfloat16 g_X1hi[(size_t)M_L1 * KDIM];
__device__ __align__(16) __nv_bfloat16 g_X1lo[(size_t)M_L1 * KDIM];
__device__ __align__(16) float         g_h1[(size_t)M_L1 * D_OUT];
__device__ __align__(16) __nv_bfloat16 g_X2hi[(size_t)BATCH * KDIM];
__device__ __align__(16) __nv_bfloat16 g_X2lo[(size_t)BATCH * KDIM];
__device__ __align__(16) __nv_bfloat16 g_W1hi[(size_t)D_OUT * KDIM];
__device__ __align__(16) __nv_bfloat16 g_W1lo[(size_t)D_OUT * KDIM];
__device__ __align__(16) __nv_bfloat16 g_W2hi[(size_t)D_OUT * KDIM];
__device__ __align__(16) __nv_bfloat16 g_W2lo[(size_t)D_OUT * KDIM];
__device__ int g_is64;

// ================= base-ISA PTX helpers (sm_103 plain, no 'a' features) ======
__device__ __forceinline__ uint32_t smem_u32(const void* p) {
    uint32_t a;
    asm("{ .reg .u64 t; cvta.to.shared.u64 t, %1; cvt.u32.u64 %0, t; }" : "=r"(a) : "l"(p));
    return a;
}
__device__ __forceinline__ void cp16(uint32_t saddr, const void* gaddr) {
    asm volatile("cp.async.cg.shared.global [%0], [%1], 16;" :: "r"(saddr), "l"(gaddr) : "memory");
}
__device__ __forceinline__ void cp_commit() {
    asm volatile("cp.async.commit_group;" ::: "memory");
}
__device__ __forceinline__ void cp_wait2() {
    asm volatile("cp.async.wait_group 2;" ::: "memory");
}
__device__ __forceinline__ void ldsm_x4(uint32_t* r, uint32_t addr) {
    asm volatile("ldmatrix.sync.aligned.m8n8.x4.shared.b16 {%0,%1,%2,%3}, [%4];"
                 : "=r"(r[0]), "=r"(r[1]), "=r"(r[2]), "=r"(r[3]) : "r"(addr));
}
__device__ __forceinline__ void mma16816(float* c, const uint32_t* a, const uint32_t* b) {
    asm volatile("mma.sync.aligned.m16n8k16.row.col.f32.bf16.bf16.f32 "
                 "{%0,%1,%2,%3}, {%4,%5,%6,%7}, {%8,%9}, {%0,%1,%2,%3};"
                 : "+f"(c[0]), "+f"(c[1]), "+f"(c[2]), "+f"(c[3])
                 : "r"(a[0]), "r"(a[1]), "r"(a[2]), "r"(a[3]), "r"(b[0]), "r"(b[1]));
}

// ---------------- index dtype probe ----------------
__global__ void detect_idx_dtype(const void* __restrict__ nb) {
    const long long* p = (const long long*)nb;
    int ok64 = 1;
    #pragma unroll
    for (int i = 0; i < 64; i++) {
        long long v = p[i];
        if (v < 0 || v >= (long long)N_NODES) ok64 = 0;
    }
    g_is64 = ok64;
}
__device__ __forceinline__ int get_idx(const void* __restrict__ p, int i) {
    if (g_is64) return (int)((const long long*)p)[i];
    return ((const int*)p)[i];
}

// ---------------- fp32 -> bf16 hi/lo split ----------------
__device__ __forceinline__ void split2(float x, __nv_bfloat16* hi, __nv_bfloat16* lo) {
    __nv_bfloat16 h = __float2bfloat16(x);
    *hi = h;
    *lo = __float2bfloat16(x - __bfloat162float(h));
}

__global__ void split_w_kernel(const float* __restrict__ W,
                               __nv_bfloat16* __restrict__ hi,
                               __nv_bfloat16* __restrict__ lo, int n) {
    int i = blockIdx.x * blockDim.x + threadIdx.x;
    if (i < n) split2(W[i], &hi[i], &lo[i]);
}

// ---------------- layer-1 gather + mean -> bf16 split ----------------
__global__ void gather1_kernel(const float* __restrict__ features,
                               const void* __restrict__ nodes_batch,
                               const void* __restrict__ neigh2,
                               const void* __restrict__ neigh1) {
    int m = blockIdx.x;
    int t = threadIdx.x;  // 0..255
    __shared__ int idx[K1 + 1];
    if (t < K1) idx[t + 1] = get_idx(neigh1, m * K1 + t);
    if (t == K1) idx[0] = (m < BATCH) ? get_idx(nodes_batch, m)
                                      : get_idx(neigh2, m - BATCH);
    __syncthreads();

    float selfv = features[(size_t)idx[0] * D_IN + t];
    float acc = 0.f;
    #pragma unroll
    for (int k = 0; k < K1; k++)
        acc += features[(size_t)idx[k + 1] * D_IN + t];

    size_t base = (size_t)m * KDIM;
    split2(selfv,            &g_X1hi[base + t],        &g_X1lo[base + t]);
    split2(acc * (1.f / K1), &g_X1hi[base + D_IN + t], &g_X1lo[base + D_IN + t]);
}

// ---------------- layer-2 concat build -> bf16 split ----------------
__global__ void build_x2_kernel() {
    int b = blockIdx.x;
    int t = threadIdx.x;
    float selfv = g_h1[(size_t)b * D_OUT + t];
    float acc = 0.f;
    #pragma unroll
    for (int j = 0; j < K2; j++)
        acc += g_h1[(size_t)(BATCH + b * K2 + j) * D_OUT + t];
    size_t base = (size_t)b * KDIM;
    split2(selfv,            &g_X2hi[base + t],         &g_X2lo[base + t]);
    split2(acc * (1.f / K2), &g_X2hi[base + D_OUT + t], &g_X2lo[base + D_OUT + t]);
}

// =========================================================================
// mma.sync bf16 GEMM: C = relu( Ahi@Whi^T + Alo@Whi^T + Ahi@Wlo^T )
// A*: [Mrows, 512] bf16 row-major, W*: [256, 512] bf16 row-major, C: f32.
// CTA: 128(M) x 256(N), 8 warps in 2x4 grid, warp tile 64x64.
// K-chunk = 32 bf16 (64B rows, padded to 80B -> conflict-free ldmatrix).
// 3-stage cp.async pipeline. 48 chunks total (3 terms x 16).
// =========================================================================
#define ASTRIDE   80
#define A_BYTES   (128 * ASTRIDE)            // 10240
#define W_BYTES   (256 * ASTRIDE)            // 20480
#define STAGE     (A_BYTES + W_BYTES)        // 30720
#define NSTAGE    3
#define GEMM_SMEM (NSTAGE * STAGE)           // 92160
#define NCHUNK    48

__global__ void __launch_bounds__(256, 1)
gemm_bf16x3_kernel(const __nv_bfloat16* __restrict__ Ahi,
                   const __nv_bfloat16* __restrict__ Alo,
                   const __nv_bfloat16* __restrict__ Whi,
                   const __nv_bfloat16* __restrict__ Wlo,
                   float* __restrict__ C, int Mrows) {
    extern __shared__ char smem[];
    const uint32_t smem_b = smem_u32(smem);
    const int tid = threadIdx.x;
    const int l   = tid & 31;
    const int wid = tid >> 5;
    const int wm  = wid >> 2;      // 0..1 (M)
    const int wn  = wid & 3;       // 0..3 (N)
    const int bm  = blockIdx.x * 128;

    // per-thread lane offsets for ldmatrix address generation
    const uint32_t a_l = (uint32_t)((l & 15) * ASTRIDE + (l >> 4) * 16);
    const uint32_t b_l = (uint32_t)((((l >> 4) & 1) * 8 + (l & 7)) * ASTRIDE
                                    + ((l >> 3) & 1) * 16);

    float acc[4][8][4];
    #pragma unroll
    for (int i = 0; i < 4; i++)
        #pragma unroll
        for (int j = 0; j < 8; j++)
            #pragma unroll
            for (int k = 0; k < 4; k++) acc[i][j][k] = 0.f;

    // ---- chunk loader: term = ck/16 (0:hi*hi 1:lo*hi 2:hi*lo), kb = (ck%16)*32
    auto issue_load = [&](int ck, int s) {
        const int term = ck >> 4;
        const int kb   = (ck & 15) * 32;
        const __nv_bfloat16* As = (term == 1) ? Alo : Ahi;
        const __nv_bfloat16* Ws = (term == 2) ? Wlo : Whi;
        const uint32_t At = smem_b + s * STAGE;
        const uint32_t Wt = At + A_BYTES;
        // A: 128 rows x 64B; thread -> row tid/2, two 16B segs
        {
            const int r  = tid >> 1;
            const int c0 = (tid & 1) * 2;
            const __nv_bfloat16* g = As + (size_t)(bm + r) * KDIM + kb;
            cp16(At + r * ASTRIDE + c0 * 16,       g + c0 * 8);
            cp16(At + r * ASTRIDE + (c0 + 1) * 16, g + (c0 + 1) * 8);
        }
        // W: 256 rows x 64B; thread -> row tid, four 16B segs
        {
            const __nv_bfloat16* g = Ws + (size_t)tid * KDIM + kb;
            #pragma unroll
            for (int c = 0; c < 4; c++)
                cp16(Wt + tid * ASTRIDE + c * 16, g + c * 8);
        }
        cp_commit();
    };

    issue_load(0, 0);
    issue_load(1, 1);
    issue_load(2, 2);

    for (int ck = 0; ck < NCHUNK; ck++) {
        const int s = ck % NSTAGE;
        cp_wait2();
        __syncthreads();

        const uint32_t At = smem_b + s * STAGE;
        const uint32_t Wt = At + A_BYTES;
        #pragma unroll
        for (int ks = 0; ks < 2; ks++) {   // two K=16 steps per 32-chunk
            uint32_t af[4][4], bf[8][2];
            const uint32_t ab = At + (uint32_t)(wm * 64 * ASTRIDE + ks * 32) + a_l;
            #pragma unroll
            for (int mf = 0; mf < 4; mf++)
                ldsm_x4(af[mf], ab + (uint32_t)(mf * 16 * ASTRIDE));
            const uint32_t bb = Wt + (uint32_t)(wn * 64 * ASTRIDE + ks * 32) + b_l;
            #pragma unroll
            for (int jp = 0; jp < 4; jp++) {
                uint32_t t4[4];
                ldsm_x4(t4, bb + (uint32_t)(jp * 16 * ASTRIDE));
                bf[2 * jp][0] = t4[0]; bf[2 * jp][1] = t4[1];
                bf[2 * jp + 1][0] = t4[2]; bf[2 * jp + 1][1] = t4[3];
            }
            #pragma unroll
            for (int mf = 0; mf < 4; mf++)
                #pragma unroll
                for (int j = 0; j < 8; j++)
                    mma16816(acc[mf][j], af[mf], bf[j]);
        }
        __syncthreads();

        const int nk = ck + NSTAGE;
        if (nk < NCHUNK) issue_load(nk, s);
        else             cp_commit();       // keep group count consistent
    }

    // ---- epilogue: fused ReLU, direct f32 stores ----
    const int g  = l >> 2;
    const int t4 = l & 3;
    #pragma unroll
    for (int mf = 0; mf < 4; mf++) {
        const int row0 = bm + wm * 64 + mf * 16 + g;
        #pragma unroll
        for (int j = 0; j < 8; j++) {
            const int col = wn * 64 + j * 8 + t4 * 2;
            float2 v0, v1;
            v0.x = fmaxf(acc[mf][j][0], 0.f);
            v0.y = fmaxf(acc[mf][j][1], 0.f);
            v1.x = fmaxf(acc[mf][j][2], 0.f);
            v1.y = fmaxf(acc[mf][j][3], 0.f);
            *(float2*)&C[(size_t)row0 * D_OUT + col]       = v0;
            *(float2*)&C[(size_t)(row0 + 8) * D_OUT + col] = v1;
        }
    }
}

// ---------------- launch ----------------
extern "C" void kernel_launch(void* const* d_in, const int* in_sizes, int n_in,
                              void* d_out, int out_size) {
    const float* features    = (const float*)d_in[0];
    const float* W1          = (const float*)d_in[1];
    const float* W2          = (const float*)d_in[2];
    const void*  nodes_batch = d_in[3];
    const void*  neigh2      = d_in[4];
    const void*  neigh1      = d_in[5];
    float* out = (float*)d_out;

    __nv_bfloat16 *pX1hi, *pX1lo, *pX2hi, *pX2lo, *pW1hi, *pW1lo, *pW2hi, *pW2lo;
    float* pH1;
    cudaGetSymbolAddress((void**)&pX1hi, g_X1hi);
    cudaGetSymbolAddress((void**)&pX1lo, g_X1lo);
    cudaGetSymbolAddress((void**)&pX2hi, g_X2hi);
    cudaGetSymbolAddress((void**)&pX2lo, g_X2lo);
    cudaGetSymbolAddress((void**)&pW1hi, g_W1hi);
    cudaGetSymbolAddress((void**)&pW1lo, g_W1lo);
    cudaGetSymbolAddress((void**)&pW2hi, g_W2hi);
    cudaGetSymbolAddress((void**)&pW2lo, g_W2lo);
    cudaGetSymbolAddress((void**)&pH1,   g_h1);

    cudaFuncSetAttribute(gemm_bf16x3_kernel,
                         cudaFuncAttributeMaxDynamicSharedMemorySize, GEMM_SMEM);

    detect_idx_dtype<<<1, 1>>>(nodes_batch);

    const int wn = D_OUT * KDIM;  // 131072
    split_w_kernel<<<(wn + 255) / 256, 256>>>(W1, pW1hi, pW1lo, wn);
    split_w_kernel<<<(wn + 255) / 256, 256>>>(W2, pW2hi, pW2lo, wn);

    gather1_kernel<<<M_L1, 256>>>(features, nodes_batch, neigh2, neigh1);

    // h1 = relu(X1 @ W1^T): [45056, 512 x3(bf16)] -> [45056, 256] f32
    gemm_bf16x3_kernel<<<M_L1 / 128, 256, GEMM_SMEM>>>(
        pX1hi, pX1lo, pW1hi, pW1lo, pH1, M_L1);

    build_x2_kernel<<<BATCH, 256>>>();

    // h2 = relu(X2 @ W2^T): [4096, 512 x3(bf16)] -> [4096, 256] f32
    gemm_bf16x3_kernel<<<BATCH / 128, 256, GEMM_SMEM>>>(
        pX2hi, pX2lo, pW2hi, pW2lo, out, BATCH);
}

// round 7
// speedup vs baseline: 1.5025x; 1.0972x over previous
#include <cuda_runtime.h>
#include <cuda_bf16.h>
#include <cstdint>

#define N_NODES 200000
#define D_IN    256
#define D_OUT   256
#define BATCH   4096
#define K1      25
#define K2      10
#define M_L1    (BATCH * (1 + K2))   // 45056
#define KDIM    512                  // concat(self, agg) width

// ---------------- scratch (no allocations allowed) ----------------
__device__ __align__(16) __nv_bfloat16 g_X1hi[(size_t)M_L1 * KDIM];
__device__ __align__(16) __nv_bfloat16 g_X1lo[(size_t)M_L1 * KDIM];
__device__ __align__(16) float         g_h1[(size_t)M_L1 * D_OUT];
__device__ __align__(16) __nv_bfloat16 g_X2hi[(size_t)BATCH * KDIM];
__device__ __align__(16) __nv_bfloat16 g_X2lo[(size_t)BATCH * KDIM];
__device__ __align__(16) __nv_bfloat16 g_W1hi[(size_t)D_OUT * KDIM];
__device__ __align__(16) __nv_bfloat16 g_W1lo[(size_t)D_OUT * KDIM];
__device__ __align__(16) __nv_bfloat16 g_W2hi[(size_t)D_OUT * KDIM];
__device__ __align__(16) __nv_bfloat16 g_W2lo[(size_t)D_OUT * KDIM];
__device__ int g_is64;

// ================= base-ISA PTX helpers (sm_103 plain, no 'a' features) ======
__device__ __forceinline__ uint32_t smem_u32(const void* p) {
    uint32_t a;
    asm("{ .reg .u64 t; cvta.to.shared.u64 t, %1; cvt.u32.u64 %0, t; }" : "=r"(a) : "l"(p));
    return a;
}
__device__ __forceinline__ void cp16(uint32_t saddr, const void* gaddr) {
    asm volatile("cp.async.cg.shared.global [%0], [%1], 16;" :: "r"(saddr), "l"(gaddr) : "memory");
}
__device__ __forceinline__ void cp_commit() {
    asm volatile("cp.async.commit_group;" ::: "memory");
}
__device__ __forceinline__ void cp_wait2() {
    asm volatile("cp.async.wait_group 2;" ::: "memory");
}
__device__ __forceinline__ void ldsm_x4(uint32_t* r, uint32_t addr) {
    asm volatile("ldmatrix.sync.aligned.m8n8.x4.shared.b16 {%0,%1,%2,%3}, [%4];"
                 : "=r"(r[0]), "=r"(r[1]), "=r"(r[2]), "=r"(r[3]) : "r"(addr));
}
__device__ __forceinline__ void mma16816(float* c, const uint32_t* a, const uint32_t* b) {
    asm volatile("mma.sync.aligned.m16n8k16.row.col.f32.bf16.bf16.f32 "
                 "{%0,%1,%2,%3}, {%4,%5,%6,%7}, {%8,%9}, {%0,%1,%2,%3};"
                 : "+f"(c[0]), "+f"(c[1]), "+f"(c[2]), "+f"(c[3])
                 : "r"(a[0]), "r"(a[1]), "r"(a[2]), "r"(a[3]), "r"(b[0]), "r"(b[1]));
}

// ---------------- index dtype probe ----------------
__global__ void detect_idx_dtype(const void* __restrict__ nb) {
    const long long* p = (const long long*)nb;
    int ok64 = 1;
    #pragma unroll
    for (int i = 0; i < 64; i++) {
        long long v = p[i];
        if (v < 0 || v >= (long long)N_NODES) ok64 = 0;
    }
    g_is64 = ok64;
}
__device__ __forceinline__ int get_idx(const void* __restrict__ p, int i) {
    if (g_is64) return (int)((const long long*)p)[i];
    return ((const int*)p)[i];
}

// ---------------- fp32 -> bf16 hi/lo split ----------------
__device__ __forceinline__ void split2(float x, __nv_bfloat16* hi, __nv_bfloat16* lo) {
    __nv_bfloat16 h = __float2bfloat16(x);
    *hi = h;
    *lo = __float2bfloat16(x - __bfloat162float(h));
}

__global__ void split_w_kernel(const float* __restrict__ W,
                               __nv_bfloat16* __restrict__ hi,
                               __nv_bfloat16* __restrict__ lo, int n) {
    int i = blockIdx.x * blockDim.x + threadIdx.x;
    if (i < n) split2(W[i], &hi[i], &lo[i]);
}

// ---------------- layer-1 gather + mean -> bf16 split (column-half pass) ----
// Each pass touches only 512B of every feature row -> table footprint per pass
// = 200K rows x 4 x 128B lines = 102 MB < L2 (126 MB) -> gather mostly L2-hits.
__global__ void __launch_bounds__(128)
gather1_half_kernel(const float* __restrict__ features,
                    const void* __restrict__ nodes_batch,
                    const void* __restrict__ neigh2,
                    const void* __restrict__ neigh1,
                    int col_base) {
    int m = blockIdx.x;
    int t = threadIdx.x;  // 0..127
    __shared__ int idx[K1 + 1];
    if (t < K1) idx[t + 1] = get_idx(neigh1, m * K1 + t);
    if (t == K1) idx[0] = (m < BATCH) ? get_idx(nodes_batch, m)
                                      : get_idx(neigh2, m - BATCH);
    __syncthreads();

    int c = col_base + t;
    float selfv = features[(size_t)idx[0] * D_IN + c];
    float acc = 0.f;
    #pragma unroll
    for (int k = 0; k < K1; k++)
        acc += features[(size_t)idx[k + 1] * D_IN + c];

    size_t base = (size_t)m * KDIM;
    split2(selfv,            &g_X1hi[base + c],        &g_X1lo[base + c]);
    split2(acc * (1.f / K1), &g_X1hi[base + D_IN + c], &g_X1lo[base + D_IN + c]);
}

// ---------------- layer-2 concat build -> bf16 split ----------------
__global__ void build_x2_kernel() {
    int b = blockIdx.x;
    int t = threadIdx.x;
    float selfv = g_h1[(size_t)b * D_OUT + t];
    float acc = 0.f;
    #pragma unroll
    for (int j = 0; j < K2; j++)
        acc += g_h1[(size_t)(BATCH + b * K2 + j) * D_OUT + t];
    size_t base = (size_t)b * KDIM;
    split2(selfv,            &g_X2hi[base + t],         &g_X2lo[base + t]);
    split2(acc * (1.f / K2), &g_X2hi[base + D_OUT + t], &g_X2lo[base + D_OUT + t]);
}

// =========================================================================
// mma.sync bf16 GEMM: C = relu( Ahi@Whi^T + Alo@Whi^T + Ahi@Wlo^T )
// CTA: 128(M) x 256(N), 8 warps 2x4, warp tile 64x64.
// K-chunk = 32 bf16 (64B rows padded to 80B -> conflict-free ldmatrix).
// 4-stage cp.async ring, prefetch depth 3, ONE __syncthreads per chunk.
// =========================================================================
#define ASTRIDE   80
#define A_BYTES   (128 * ASTRIDE)            // 10240
#define W_BYTES   (256 * ASTRIDE)            // 20480
#define STAGE     (A_BYTES + W_BYTES)        // 30720
#define NSTAGE    4
#define GEMM_SMEM (NSTAGE * STAGE)           // 122880
#define NCHUNK    48

__global__ void __launch_bounds__(256, 1)
gemm_bf16x3_kernel(const __nv_bfloat16* __restrict__ Ahi,
                   const __nv_bfloat16* __restrict__ Alo,
                   const __nv_bfloat16* __restrict__ Whi,
                   const __nv_bfloat16* __restrict__ Wlo,
                   float* __restrict__ C, int Mrows) {
    extern __shared__ char smem[];
    const uint32_t smem_b = smem_u32(smem);
    const int tid = threadIdx.x;
    const int l   = tid & 31;
    const int wid = tid >> 5;
    const int wm  = wid >> 2;      // 0..1 (M)
    const int wn  = wid & 3;       // 0..3 (N)
    const int bm  = blockIdx.x * 128;

    const uint32_t a_l = (uint32_t)((l & 15) * ASTRIDE + (l >> 4) * 16);
    const uint32_t b_l = (uint32_t)((((l >> 4) & 1) * 8 + (l & 7)) * ASTRIDE
                                    + ((l >> 3) & 1) * 16);

    float acc[4][8][4];
    #pragma unroll
    for (int i = 0; i < 4; i++)
        #pragma unroll
        for (int j = 0; j < 8; j++)
            #pragma unroll
            for (int k = 0; k < 4; k++) acc[i][j][k] = 0.f;

    // chunk loader: term = ck/16 (0:hi*hi 1:lo*hi 2:hi*lo), kb = (ck%16)*32
    auto issue_load = [&](int ck) {
        const int s    = ck & (NSTAGE - 1);
        const int term = ck >> 4;
        const int kb   = (ck & 15) * 32;
        const __nv_bfloat16* As = (term == 1) ? Alo : Ahi;
        const __nv_bfloat16* Ws = (term == 2) ? Wlo : Whi;
        const uint32_t At = smem_b + s * STAGE;
        const uint32_t Wt = At + A_BYTES;
        {   // A: 128 rows x 64B; thread -> row tid/2, two 16B segs
            const int r  = tid >> 1;
            const int c0 = (tid & 1) * 2;
            const __nv_bfloat16* g = As + (size_t)(bm + r) * KDIM + kb;
            cp16(At + r * ASTRIDE + c0 * 16,       g + c0 * 8);
            cp16(At + r * ASTRIDE + (c0 + 1) * 16, g + (c0 + 1) * 8);
        }
        {   // W: 256 rows x 64B; thread -> row tid, four 16B segs
            const __nv_bfloat16* g = Ws + (size_t)tid * KDIM + kb;
            #pragma unroll
            for (int c = 0; c < 4; c++)
                cp16(Wt + tid * ASTRIDE + c * 16, g + c * 8);
        }
        cp_commit();
    };

    issue_load(0);
    issue_load(1);
    issue_load(2);

    for (int ck = 0; ck < NCHUNK; ck++) {
        const int s = ck & (NSTAGE - 1);
        cp_wait2();          // chunk ck landed
        __syncthreads();     // all warps done with chunk ck-1's stage

        const int nk = ck + 3;
        if (nk < NCHUNK) issue_load(nk);   // writes stage (ck-1)%4 — fenced above
        else             cp_commit();      // keep group counts consistent

        const uint32_t At = smem_b + s * STAGE;
        const uint32_t Wt = At + A_BYTES;
        #pragma unroll
        for (int ks = 0; ks < 2; ks++) {
            uint32_t af[4][4], bf[8][2];
            const uint32_t ab = At + (uint32_t)(wm * 64 * ASTRIDE + ks * 32) + a_l;
            #pragma unroll
            for (int mf = 0; mf < 4; mf++)
                ldsm_x4(af[mf], ab + (uint32_t)(mf * 16 * ASTRIDE));
            const uint32_t bb = Wt + (uint32_t)(wn * 64 * ASTRIDE + ks * 32) + b_l;
            #pragma unroll
            for (int jp = 0; jp < 4; jp++) {
                uint32_t t4[4];
                ldsm_x4(t4, bb + (uint32_t)(jp * 16 * ASTRIDE));
                bf[2 * jp][0] = t4[0]; bf[2 * jp][1] = t4[1];
                bf[2 * jp + 1][0] = t4[2]; bf[2 * jp + 1][1] = t4[3];
            }
            #pragma unroll
            for (int mf = 0; mf < 4; mf++)
                #pragma unroll
                for (int j = 0; j < 8; j++)
                    mma16816(acc[mf][j], af[mf], bf[j]);
        }
    }

    // ---- epilogue: fused ReLU, direct f32 stores ----
    const int g  = l >> 2;
    const int t4 = l & 3;
    #pragma unroll
    for (int mf = 0; mf < 4; mf++) {
        const int row0 = bm + wm * 64 + mf * 16 + g;
        #pragma unroll
        for (int j = 0; j < 8; j++) {
            const int col = wn * 64 + j * 8 + t4 * 2;
            float2 v0, v1;
            v0.x = fmaxf(acc[mf][j][0], 0.f);
            v0.y = fmaxf(acc[mf][j][1], 0.f);
            v1.x = fmaxf(acc[mf][j][2], 0.f);
            v1.y = fmaxf(acc[mf][j][3], 0.f);
            *(float2*)&C[(size_t)row0 * D_OUT + col]       = v0;
            *(float2*)&C[(size_t)(row0 + 8) * D_OUT + col] = v1;
        }
    }
}

// ---------------- launch ----------------
extern "C" void kernel_launch(void* const* d_in, const int* in_sizes, int n_in,
                              void* d_out, int out_size) {
    const float* features    = (const float*)d_in[0];
    const float* W1          = (const float*)d_in[1];
    const float* W2          = (const float*)d_in[2];
    const void*  nodes_batch = d_in[3];
    const void*  neigh2      = d_in[4];
    const void*  neigh1      = d_in[5];
    float* out = (float*)d_out;

    __nv_bfloat16 *pX1hi, *pX1lo, *pX2hi, *pX2lo, *pW1hi, *pW1lo, *pW2hi, *pW2lo;
    float* pH1;
    cudaGetSymbolAddress((void**)&pX1hi, g_X1hi);
    cudaGetSymbolAddress((void**)&pX1lo, g_X1lo);
    cudaGetSymbolAddress((void**)&pX2hi, g_X2hi);
    cudaGetSymbolAddress((void**)&pX2lo, g_X2lo);
    cudaGetSymbolAddress((void**)&pW1hi, g_W1hi);
    cudaGetSymbolAddress((void**)&pW1lo, g_W1lo);
    cudaGetSymbolAddress((void**)&pW2hi, g_W2hi);
    cudaGetSymbolAddress((void**)&pW2lo, g_W2lo);
    cudaGetSymbolAddress((void**)&pH1,   g_h1);

    cudaFuncSetAttribute(gemm_bf16x3_kernel,
                         cudaFuncAttributeMaxDynamicSharedMemorySize, GEMM_SMEM);

    detect_idx_dtype<<<1, 1>>>(nodes_batch);

    const int wn = D_OUT * KDIM;  // 131072
    split_w_kernel<<<(wn + 255) / 256, 256>>>(W1, pW1hi, pW1lo, wn);
    split_w_kernel<<<(wn + 255) / 256, 256>>>(W2, pW2hi, pW2lo, wn);

    // gather in two column-half passes for L2 residency of the feature table
    gather1_half_kernel<<<M_L1, 128>>>(features, nodes_batch, neigh2, neigh1, 0);
    gather1_half_kernel<<<M_L1, 128>>>(features, nodes_batch, neigh2, neigh1, 128);

    // h1 = relu(X1 @ W1^T): [45056, 512 x3(bf16)] -> [45056, 256] f32
    gemm_bf16x3_kernel<<<M_L1 / 128, 256, GEMM_SMEM>>>(
        pX1hi, pX1lo, pW1hi, pW1lo, pH1, M_L1);

    build_x2_kernel<<<BATCH, 256>>>();

    // h2 = relu(X2 @ W2^T): [4096, 512 x3(bf16)] -> [4096, 256] f32
    gemm_bf16x3_kernel<<<BATCH / 128, 256, GEMM_SMEM>>>(
        pX2hi, pX2lo, pW2hi, pW2lo, out, BATCH);
}

// round 8
// speedup vs baseline: 1.8801x; 1.2514x over previous
#include <cuda_runtime.h>
#include <cuda_bf16.h>
#include <cstdint>

#define N_NODES 200000
#define D_IN    256
#define D_OUT   256
#define BATCH   4096
#define K1      25
#define K2      10
#define M_L1    (BATCH * (1 + K2))   // 45056
#define KDIM    512                  // concat(self, agg) width

// ---------------- scratch (no allocations allowed) ----------------
__device__ __align__(16) __nv_bfloat16 g_X1hi[(size_t)M_L1 * KDIM];
__device__ __align__(16) __nv_bfloat16 g_X1lo[(size_t)M_L1 * KDIM];
__device__ __align__(16) float         g_h1[(size_t)M_L1 * D_OUT];
__device__ __align__(16) __nv_bfloat16 g_X2hi[(size_t)BATCH * KDIM];
__device__ __align__(16) __nv_bfloat16 g_X2lo[(size_t)BATCH * KDIM];
__device__ __align__(16) __nv_bfloat16 g_W1hi[(size_t)D_OUT * KDIM];
__device__ __align__(16) __nv_bfloat16 g_W1lo[(size_t)D_OUT * KDIM];
__device__ __align__(16) __nv_bfloat16 g_W2hi[(size_t)D_OUT * KDIM];
__device__ __align__(16) __nv_bfloat16 g_W2lo[(size_t)D_OUT * KDIM];
__device__ int g_is64;

// ================= base-ISA PTX helpers (sm_103 plain, no 'a' features) ======
__device__ __forceinline__ uint32_t smem_u32(const void* p) {
    uint32_t a;
    asm("{ .reg .u64 t; cvta.to.shared.u64 t, %1; cvt.u32.u64 %0, t; }" : "=r"(a) : "l"(p));
    return a;
}
__device__ __forceinline__ void cp16(uint32_t saddr, const void* gaddr) {
    asm volatile("cp.async.cg.shared.global [%0], [%1], 16;" :: "r"(saddr), "l"(gaddr) : "memory");
}
__device__ __forceinline__ void cp_commit() {
    asm volatile("cp.async.commit_group;" ::: "memory");
}
__device__ __forceinline__ void cp_wait1() {
    asm volatile("cp.async.wait_group 1;" ::: "memory");
}
__device__ __forceinline__ void ldsm_x4(uint32_t* r, uint32_t addr) {
    asm volatile("ldmatrix.sync.aligned.m8n8.x4.shared.b16 {%0,%1,%2,%3}, [%4];"
                 : "=r"(r[0]), "=r"(r[1]), "=r"(r[2]), "=r"(r[3]) : "r"(addr));
}
__device__ __forceinline__ void mma16816(float* c, const uint32_t* a, const uint32_t* b) {
    asm volatile("mma.sync.aligned.m16n8k16.row.col.f32.bf16.bf16.f32 "
                 "{%0,%1,%2,%3}, {%4,%5,%6,%7}, {%8,%9}, {%0,%1,%2,%3};"
                 : "+f"(c[0]), "+f"(c[1]), "+f"(c[2]), "+f"(c[3])
                 : "r"(a[0]), "r"(a[1]), "r"(a[2]), "r"(a[3]), "r"(b[0]), "r"(b[1]));
}

__device__ __forceinline__ int get_idx(const void* __restrict__ p, int i) {
    if (g_is64) return (int)((const long long*)p)[i];
    return ((const int*)p)[i];
}

// ---------------- fp32 -> bf16 hi/lo split ----------------
__device__ __forceinline__ void split2(float x, __nv_bfloat16* hi, __nv_bfloat16* lo) {
    __nv_bfloat16 h = __float2bfloat16(x);
    *hi = h;
    *lo = __float2bfloat16(x - __bfloat162float(h));
}

// ---------------- launch #1: split BOTH weight matrices + index-dtype probe --
__global__ void split_w_detect_kernel(const float* __restrict__ W1,
                                      const float* __restrict__ W2,
                                      const void* __restrict__ nb) {
    // dtype probe (one thread; same launch precedes all consumers)
    if (blockIdx.x == 0 && threadIdx.x == 0) {
        const long long* p = (const long long*)nb;
        int ok64 = 1;
        #pragma unroll
        for (int i = 0; i < 64; i++) {
            long long v = p[i];
            if (v < 0 || v >= (long long)N_NODES) ok64 = 0;
        }
        g_is64 = ok64;
    }
    const int n = D_OUT * KDIM;  // 131072 per matrix
    int i = blockIdx.x * blockDim.x + threadIdx.x;
    if (i < n) {
        split2(W1[i], &g_W1hi[i], &g_W1lo[i]);
        split2(W2[i], &g_W2hi[i], &g_W2lo[i]);
    }
}

// ---------------- launches #2,#3: layer-1 gather + mean (column-half) -------
// Each pass touches 512B of every feature row -> per-pass table footprint
// 102 MB < L2 (126 MB) -> gather mostly L2-hits.
__global__ void __launch_bounds__(128)
gather1_half_kernel(const float* __restrict__ features,
                    const void* __restrict__ nodes_batch,
                    const void* __restrict__ neigh2,
                    const void* __restrict__ neigh1,
                    int col_base) {
    int m = blockIdx.x;
    int t = threadIdx.x;  // 0..127
    __shared__ int idx[K1 + 1];
    if (t < K1) idx[t + 1] = get_idx(neigh1, m * K1 + t);
    if (t == K1) idx[0] = (m < BATCH) ? get_idx(nodes_batch, m)
                                      : get_idx(neigh2, m - BATCH);
    __syncthreads();

    int c = col_base + t;
    float selfv = features[(size_t)idx[0] * D_IN + c];
    float acc = 0.f;
    #pragma unroll
    for (int k = 0; k < K1; k++)
        acc += features[(size_t)idx[k + 1] * D_IN + c];

    size_t base = (size_t)m * KDIM;
    split2(selfv,            &g_X1hi[base + c],        &g_X1lo[base + c]);
    split2(acc * (1.f / K1), &g_X1hi[base + D_IN + c], &g_X1lo[base + D_IN + c]);
}

// ---------------- layer-2 concat build -> bf16 split ----------------
__global__ void build_x2_kernel() {
    int b = blockIdx.x;
    int t = threadIdx.x;
    float selfv = g_h1[(size_t)b * D_OUT + t];
    float acc = 0.f;
    #pragma unroll
    for (int j = 0; j < K2; j++)
        acc += g_h1[(size_t)(BATCH + b * K2 + j) * D_OUT + t];
    size_t base = (size_t)b * KDIM;
    split2(selfv,            &g_X2hi[base + t],         &g_X2lo[base + t]);
    split2(acc * (1.f / K2), &g_X2hi[base + D_OUT + t], &g_X2lo[base + D_OUT + t]);
}

// =========================================================================
// mma.sync bf16 GEMM: C = relu( Ahi@Whi^T + Ahi@Wlo^T + Alo@Whi^T )
// CTA: 128(M) x 128(N), 8 warps 2x4, warp tile 64x32.
// 60KB smem, ~110 regs -> 2 CTAs/SM (16 warps/SM) for latency hiding.
// K-chunk = 32 bf16 (64B rows padded to 80B -> conflict-free ldmatrix).
// 3-stage cp.async ring, prefetch 2, ONE __syncthreads per chunk.
// Chunk order kb-major: (hi,Whi),(hi,Wlo),(lo,Whi) -> A-hi tile L2-hot reuse.
// =========================================================================
#define ASTRIDE   80
#define A_BYTES   (128 * ASTRIDE)            // 10240
#define W_BYTES   (128 * ASTRIDE)            // 10240
#define STAGE     (A_BYTES + W_BYTES)        // 20480
#define NSTAGE    3
#define GEMM_SMEM (NSTAGE * STAGE)           // 61440
#define NCHUNK    48

__global__ void __launch_bounds__(256, 2)
gemm_bf16x3_kernel(const __nv_bfloat16* __restrict__ Ahi,
                   const __nv_bfloat16* __restrict__ Alo,
                   const __nv_bfloat16* __restrict__ Whi,
                   const __nv_bfloat16* __restrict__ Wlo,
                   float* __restrict__ C) {
    extern __shared__ char smem[];
    const uint32_t smem_b = smem_u32(smem);
    const int tid = threadIdx.x;
    const int l   = tid & 31;
    const int wid = tid >> 5;
    const int wm  = wid >> 2;      // 0..1 (M)
    const int wn  = wid & 3;       // 0..3 (N)
    const int bm  = (blockIdx.x >> 1) * 128;       // M tile
    const int bn  = (blockIdx.x & 1) * 128;        // N half

    const uint32_t a_l = (uint32_t)((l & 15) * ASTRIDE + (l >> 4) * 16);
    const uint32_t b_l = (uint32_t)((((l >> 4) & 1) * 8 + (l & 7)) * ASTRIDE
                                    + ((l >> 3) & 1) * 16);

    float acc[4][4][4];
    #pragma unroll
    for (int i = 0; i < 4; i++)
        #pragma unroll
        for (int j = 0; j < 4; j++)
            #pragma unroll
            for (int k = 0; k < 4; k++) acc[i][j][k] = 0.f;

    // chunk ck: kb-major, term = ck%3: 0:(Ahi,Whi) 1:(Ahi,Wlo) 2:(Alo,Whi)
    auto issue_load = [&](int ck) {
        const int s    = ck % NSTAGE;
        const int term = ck % 3;
        const int kb   = (ck / 3) * 32;
        const __nv_bfloat16* As = (term == 2) ? Alo : Ahi;
        const __nv_bfloat16* Ws = (term == 1) ? Wlo : Whi;
        const uint32_t At = smem_b + s * STAGE;
        const uint32_t Wt = At + A_BYTES;
        const int r  = tid >> 1;
        const int c0 = (tid & 1) * 2;
        {   // A: 128 rows x 64B; thread -> row tid/2, two 16B segs
            const __nv_bfloat16* g = As + (size_t)(bm + r) * KDIM + kb;
            cp16(At + r * ASTRIDE + c0 * 16,       g + c0 * 8);
            cp16(At + r * ASTRIDE + (c0 + 1) * 16, g + (c0 + 1) * 8);
        }
        {   // W: 128 rows (this CTA's N half) x 64B
            const __nv_bfloat16* g = Ws + (size_t)(bn + r) * KDIM + kb;
            cp16(Wt + r * ASTRIDE + c0 * 16,       g + c0 * 8);
            cp16(Wt + r * ASTRIDE + (c0 + 1) * 16, g + (c0 + 1) * 8);
        }
        cp_commit();
    };

    issue_load(0);
    issue_load(1);

    for (int ck = 0; ck < NCHUNK; ck++) {
        const int s = ck % NSTAGE;
        cp_wait1();          // chunk ck landed (<=1 group pending)
        __syncthreads();     // all warps done with chunk ck-1's stage

        const int nk = ck + 2;
        if (nk < NCHUNK) issue_load(nk);   // writes stage (ck-1)%3 — fenced above
        else             cp_commit();      // keep group counts consistent

        const uint32_t At = smem_b + s * STAGE;
        const uint32_t Wt = At + A_BYTES;
        #pragma unroll
        for (int ks = 0; ks < 2; ks++) {
            uint32_t af[4][4], bf[4][2];
            const uint32_t ab = At + (uint32_t)(wm * 64 * ASTRIDE + ks * 32) + a_l;
            #pragma unroll
            for (int mf = 0; mf < 4; mf++)
                ldsm_x4(af[mf], ab + (uint32_t)(mf * 16 * ASTRIDE));
            const uint32_t bb = Wt + (uint32_t)(wn * 32 * ASTRIDE + ks * 32) + b_l;
            #pragma unroll
            for (int jp = 0; jp < 2; jp++) {
                uint32_t t4[4];
                ldsm_x4(t4, bb + (uint32_t)(jp * 16 * ASTRIDE));
                bf[2 * jp][0] = t4[0]; bf[2 * jp][1] = t4[1];
                bf[2 * jp + 1][0] = t4[2]; bf[2 * jp + 1][1] = t4[3];
            }
            #pragma unroll
            for (int mf = 0; mf < 4; mf++)
                #pragma unroll
                for (int j = 0; j < 4; j++)
                    mma16816(acc[mf][j], af[mf], bf[j]);
        }
    }

    // ---- epilogue: fused ReLU, direct f32 stores ----
    const int g  = l >> 2;
    const int t4 = l & 3;
    #pragma unroll
    for (int mf = 0; mf < 4; mf++) {
        const int row0 = bm + wm * 64 + mf * 16 + g;
        #pragma unroll
        for (int j = 0; j < 4; j++) {
            const int col = bn + wn * 32 + j * 8 + t4 * 2;
            float2 v0, v1;
            v0.x = fmaxf(acc[mf][j][0], 0.f);
            v0.y = fmaxf(acc[mf][j][1], 0.f);
            v1.x = fmaxf(acc[mf][j][2], 0.f);
            v1.y = fmaxf(acc[mf][j][3], 0.f);
            *(float2*)&C[(size_t)row0 * D_OUT + col]       = v0;
            *(float2*)&C[(size_t)(row0 + 8) * D_OUT + col] = v1;
        }
    }
}

// ---------------- launch ----------------
extern "C" void kernel_launch(void* const* d_in, const int* in_sizes, int n_in,
                              void* d_out, int out_size) {
    const float* features    = (const float*)d_in[0];
    const float* W1          = (const float*)d_in[1];
    const float* W2          = (const float*)d_in[2];
    const void*  nodes_batch = d_in[3];
    const void*  neigh2      = d_in[4];
    const void*  neigh1      = d_in[5];
    float* out = (float*)d_out;

    __nv_bfloat16 *pX1hi, *pX1lo, *pX2hi, *pX2lo, *pW1hi, *pW1lo, *pW2hi, *pW2lo;
    float* pH1;
    cudaGetSymbolAddress((void**)&pX1hi, g_X1hi);
    cudaGetSymbolAddress((void**)&pX1lo, g_X1lo);
    cudaGetSymbolAddress((void**)&pX2hi, g_X2hi);
    cudaGetSymbolAddress((void**)&pX2lo, g_X2lo);
    cudaGetSymbolAddress((void**)&pW1hi, g_W1hi);
    cudaGetSymbolAddress((void**)&pW1lo, g_W1lo);
    cudaGetSymbolAddress((void**)&pW2hi, g_W2hi);
    cudaGetSymbolAddress((void**)&pW2lo, g_W2lo);
    cudaGetSymbolAddress((void**)&pH1,   g_h1);

    cudaFuncSetAttribute(gemm_bf16x3_kernel,
                         cudaFuncAttributeMaxDynamicSharedMemorySize, GEMM_SMEM);

    // Launch #1: both W splits + dtype probe (one kernel)
    split_w_detect_kernel<<<(D_OUT * KDIM + 255) / 256, 256>>>(W1, W2, nodes_batch);

    // Launches #2,#3: gather (two column-half passes for L2 residency)
    gather1_half_kernel<<<M_L1, 128>>>(features, nodes_batch, neigh2, neigh1, 0);
    gather1_half_kernel<<<M_L1, 128>>>(features, nodes_batch, neigh2, neigh1, 128);

    // Launch #4 (ncu-captured slot): h1 = relu(X1 @ W1^T)
    gemm_bf16x3_kernel<<<(M_L1 / 128) * 2, 256, GEMM_SMEM>>>(
        pX1hi, pX1lo, pW1hi, pW1lo, pH1);

    // Launch #5
    build_x2_kernel<<<BATCH, 256>>>();

    // Launch #6: h2 = relu(X2 @ W2^T)
    gemm_bf16x3_kernel<<<(BATCH / 128) * 2, 256, GEMM_SMEM>>>(
        pX2hi, pX2lo, pW2hi, pW2lo, out);
}